// round 17
// baseline (speedup 1.0000x reference)
#include <cuda_runtime.h>
#include <math.h>

// Petrosian fractal features, 5 scales, T=4096, 57 windows/row.
// One WARP per row, 8 rows/CTA, no smem, no __syncthreads.
// Row = 16 chunks of 256 elems; each lane owns 8 consecutive elems loaded
// with ONE 256-bit LDG (ld.global.nc.v8.b32) per chunk (2-chunk rotating
// prefetch = 64B in flight/lane). Halo = next lane's first two elems via
// circular shfl; chunk-end boundary deferred one iteration (lane 31 carries).
// Segment sums (128 elems = 16 lanes) via one packed __reduce_add_sync
// (lanes<16 -> low 16 bits, lanes>=16 -> high 16 bits).
// Windows: zc([128a,128b)) = S[b] - S[a] - bcorr[b].

#define T_LEN 4096
#define N_WIN 57
#define WARPS 8
#define FULL  0xffffffffu

struct F8 { float v[8]; };

__device__ __forceinline__ F8 ld256(const float* p) {
    unsigned a0,a1,a2,a3,a4,a5,a6,a7;
    asm("ld.global.nc.v8.b32 {%0,%1,%2,%3,%4,%5,%6,%7}, [%8];"
        : "=r"(a0),"=r"(a1),"=r"(a2),"=r"(a3),
          "=r"(a4),"=r"(a5),"=r"(a6),"=r"(a7)
        : "l"(p));
    F8 r;
    r.v[0]=__uint_as_float(a0); r.v[1]=__uint_as_float(a1);
    r.v[2]=__uint_as_float(a2); r.v[3]=__uint_as_float(a3);
    r.v[4]=__uint_as_float(a4); r.v[5]=__uint_as_float(a5);
    r.v[6]=__uint_as_float(a6); r.v[7]=__uint_as_float(a7);
    return r;
}

__global__ __launch_bounds__(256)
void petrosian_kernel(const float* __restrict__ x, float* __restrict__ out) {
    const int lane = threadIdx.x & 31;
    const int wid  = threadIdx.x >> 5;
    const int row  = blockIdx.x * WARPS + wid;

    const float* rowp = x + (size_t)row * T_LEN;

    // 2-chunk rotating prefetch (2 LDG.256 = 64B in flight per lane)
    F8 buf[2];
    buf[0] = ld256(rowp + 8 * lane);
    buf[1] = ld256(rowp + 256 + 8 * lane);

    int   segreg = 0, bcreg = 0;   // lane m: segment-m sum / bcorr[m+1]
    int   prevHigh = 0;
    float cx = 0.0f, cd = 0.0f;    // lane 31 carries: x[255], d[254] of prev chunk
    const int nl = (lane + 1) & 31;

    #pragma unroll
    for (int c = 0; c < 16; c++) {
        F8 w = buf[c & 1];
        if (c < 14) buf[c & 1] = ld256(rowp + 256 * (c + 2) + 8 * lane);

        // halo: next lane's first two elems (lane31 gets lane0's = x[256c], x[256c+1])
        float h0 = __shfl_sync(FULL, w.v[0], nl);
        float h1 = __shfl_sync(FULL, w.v[1], nl);

        // deferred end-boundary of previous chunk: s[256c-2], s[256c-1]
        if (c > 0) {
            float dA = h0 - cx;       // d[256c-1]   (valid at lane 31)
            float dB = h1 - h0;       // d[256c]
            int t31 = ((cd * dA < 0.0f) ? 1 : 0) + ((dA * dB < 0.0f) ? 1 : 0);
            int te = __shfl_sync(FULL, t31, 31);
            if (lane == 2 * c - 1) { segreg = prevHigh + te; bcreg = te; }
        }

        // indicators j = 256c + 8l + {0..7}
        float d0 = w.v[1]-w.v[0], d1 = w.v[2]-w.v[1], d2 = w.v[3]-w.v[2];
        float d3 = w.v[4]-w.v[3], d4 = w.v[5]-w.v[4], d5 = w.v[6]-w.v[5];
        float d6 = w.v[7]-w.v[6], d7 = h0 - w.v[7],   d8 = h1 - h0;
        int cnt = ((d0*d1<0.0f)?1:0) + ((d1*d2<0.0f)?1:0) + ((d2*d3<0.0f)?1:0)
                + ((d3*d4<0.0f)?1:0) + ((d4*d5<0.0f)?1:0) + ((d5*d6<0.0f)?1:0);
        int s6 = (d6*d7<0.0f)?1:0, s7 = (d7*d8<0.0f)?1:0;
        if (lane < 31) cnt += s6 + s7;            // lane31's last two deferred
        int tm = __shfl_sync(FULL, s6 + s7, 15);  // s[126]+s[127] = bcorr[2c+1]

        // packed dual-segment sum: lanes 0-15 -> seg 2c, lanes 16-31 -> seg 2c+1
        int contrib = (lane < 16) ? cnt : (cnt << 16);
        int total = __reduce_add_sync(FULL, contrib);
        if (lane == 2 * c) { segreg = total & 0xFFFF; bcreg = tm; }
        prevHigh = total >> 16;

        cx = w.v[7];   // lane31: x[256c+255]
        cd = d6;       // lane31: d[256c+254]
    }
    // final high segment (m=31): s[4094], s[4095] invalid
    if (lane == 31) { segreg = prevHigh; bcreg = 0; }

    // inclusive scan: sc at lane l = S[l+1]
    int sc = segreg;
    #pragma unroll
    for (int off = 1; off < 32; off <<= 1) {
        int n = __shfl_up_sync(FULL, sc, off);
        if (lane >= off) sc += n;
    }

    // 57 outputs, 2 per lane
    const size_t obase = (size_t)row * N_WIN;
    #pragma unroll
    for (int half = 0; half < 2; half++) {
        int k  = lane + half * 32;
        int kk = (k < N_WIN) ? k : 0;
        int w_, a; float L;
        if      (kk < 1)  { w_ = 4096; a = 0;             L = 3.612359948f; }
        else if (kk < 4)  { w_ = 2048; a = (kk - 1) * 8;  L = 3.311329954f; }
        else if (kk < 11) { w_ = 1024; a = (kk - 4) * 4;  L = 3.010299957f; }
        else if (kk < 26) { w_ = 512;  a = (kk - 11) * 2; L = 2.709269961f; }
        else              { w_ = 256;  a = kk - 26;       L = 2.408239965f; }
        int b = a + (w_ >> 7);

        int Sb = __shfl_sync(FULL, sc, b - 1);
        int Sa = __shfl_sync(FULL, sc, (a > 0) ? (a - 1) : 0);
        if (a == 0) Sa = 0;
        int bc = __shfl_sync(FULL, bcreg, b - 1);

        if (k < N_WIN) {
            float zc = (float)(Sb - Sa - bc);
            float wf = (float)w_;
            float denom = L + log10f(wf / (wf + 0.4f * zc));
            out[obase + k] = L / denom;
        }
    }
}

extern "C" void kernel_launch(void* const* d_in, const int* in_sizes, int n_in,
                              void* d_out, int out_size) {
    const float* x = (const float*)d_in[0];
    float* out = (float*)d_out;
    int n_rows = in_sizes[0] / T_LEN;               // B*C = 4096
    int n_blocks = n_rows / WARPS;                  // 512
    petrosian_kernel<<<n_blocks, 256>>>(x, out);
}